// round 4
// baseline (speedup 1.0000x reference)
#include <cuda_runtime.h>
#include <cuda_bf16.h>
#include <cstdint>

// Problem dims
#define MDIM 4096       // batch
#define KDIM 4096       // IN_F * 32
#define NDIM 4096       // OUT_F * 32
#define BM 128
#define BN 128
#define BK 32
#define KTILES (KDIM / BK)   // 128
#define STAGES 4

// SMEM tile geometry: rows of 32 bf16 = 64B data, padded to 80B stride
// (20*r mod 32 is a permutation for r in 0..7 -> conflict-free ldmatrix)
#define ROW_BYTES 80
#define TILE_BYTES (128 * ROW_BYTES)          // 10240
#define STAGE_BYTES (4 * TILE_BYTES)          // Ahi|Alo|Bhi|Blo = 40960
#define SMEM_BYTES (STAGES * STAGE_BYTES)     // 163840

// 128 MB static scratch (sanctioned __device__ globals)
__device__ __align__(128) __nv_bfloat16 g_Ahi[(size_t)MDIM * KDIM];
__device__ __align__(128) __nv_bfloat16 g_Alo[(size_t)MDIM * KDIM];
__device__ __align__(128) __nv_bfloat16 g_Bhi[(size_t)NDIM * KDIM];
__device__ __align__(128) __nv_bfloat16 g_Blo[(size_t)NDIM * KDIM];

// ---------------- helpers ----------------
__device__ __forceinline__ uint32_t smem_u32(const void* p) {
    uint32_t a;
    asm("{ .reg .u64 t; cvta.to.shared.u64 t, %1; cvt.u32.u64 %0, t; }" : "=r"(a) : "l"(p));
    return a;
}
__device__ __forceinline__ void cp_async16(uint32_t s, const void* g) {
    asm volatile("cp.async.cg.shared.global [%0], [%1], 16;" :: "r"(s), "l"(g));
}
#define CP_COMMIT() asm volatile("cp.async.commit_group;" ::: "memory")
#define CP_WAIT2()  asm volatile("cp.async.wait_group 2;" ::: "memory")

__device__ __forceinline__ void ldsm4(uint32_t (&r)[4], uint32_t addr) {
    asm volatile("ldmatrix.sync.aligned.m8n8.x4.shared.b16 {%0,%1,%2,%3}, [%4];"
                 : "=r"(r[0]), "=r"(r[1]), "=r"(r[2]), "=r"(r[3]) : "r"(addr));
}
__device__ __forceinline__ void mma16816(float (&c)[4], const uint32_t (&a)[4],
                                         uint32_t b0, uint32_t b1) {
    asm volatile("mma.sync.aligned.m16n8k16.row.col.f32.bf16.bf16.f32 "
                 "{%0,%1,%2,%3}, {%4,%5,%6,%7}, {%8,%9}, {%0,%1,%2,%3};"
                 : "+f"(c[0]), "+f"(c[1]), "+f"(c[2]), "+f"(c[3])
                 : "r"(a[0]), "r"(a[1]), "r"(a[2]), "r"(a[3]), "r"(b0), "r"(b1));
}

__device__ __forceinline__ unsigned short bf16_bits(__nv_bfloat16 h) {
    return *reinterpret_cast<unsigned short*>(&h);
}
__device__ __forceinline__ void split1(float v, __nv_bfloat16& h, __nv_bfloat16& l) {
    h = __float2bfloat16(v);
    l = __float2bfloat16(v - __bfloat162float(h));
}

// ---------------- pre-kernels ----------------
__global__ void k_split_x(const float4* __restrict__ x) {
    unsigned i = blockIdx.x * blockDim.x + threadIdx.x;   // 0 .. 4M-1
    float4 v = x[i];
    __nv_bfloat16 h0, h1, h2, h3, l0, l1, l2, l3;
    split1(v.x, h0, l0); split1(v.y, h1, l1); split1(v.z, h2, l2); split1(v.w, h3, l3);
    ushort4 H = make_ushort4(bf16_bits(h0), bf16_bits(h1), bf16_bits(h2), bf16_bits(h3));
    ushort4 L = make_ushort4(bf16_bits(l0), bf16_bits(l1), bf16_bits(l2), bf16_bits(l3));
    reinterpret_cast<ushort4*>(g_Ahi)[i] = H;
    reinterpret_cast<ushort4*>(g_Alo)[i] = L;
}

// Bbig[n = o*32+k, kdim = f*32+i] = sign(i, i^k) * W[o, f, i^k]
__global__ void k_build_w(const float* __restrict__ w) {
    unsigned idx = blockIdx.x * blockDim.x + threadIdx.x; // 0 .. 16M-1
    unsigned col = idx & 4095u;        // kdim
    unsigned row = idx >> 12;          // n
    unsigned i = col & 31u, f = col >> 5;
    unsigned k = row & 31u, o = row >> 5;
    unsigned j = i ^ k;
    float v = w[(o * 128u + f) * 32u + j];
    // reorder sign: sum popc((i>>t) & j), t=1..4 ; metric: bit 4 of (i & j) (sig[4] = -1)
    unsigned s = __popc((i >> 1) & j) + __popc((i >> 2) & j) +
                 __popc((i >> 3) & j) + __popc((i >> 4) & j);
    s += (i & j) >> 4;
    if (s & 1u) v = -v;
    __nv_bfloat16 h, l;
    split1(v, h, l);
    g_Bhi[idx] = h;
    g_Blo[idx] = l;
}

// ---------------- GEMM (mma.sync bf16, 3-term split) ----------------
__device__ __forceinline__ void load_stage(uint32_t sbase, int slot, int m0, int n0,
                                           int k0, int tid) {
    const uint32_t so = sbase + slot * STAGE_BYTES;
    const __nv_bfloat16* srcs[4] = {g_Ahi, g_Alo, g_Bhi, g_Blo};
    const int rows[4] = {m0, m0, n0, n0};
#pragma unroll
    for (int t4 = 0; t4 < 4; t4++) {
        const char* gb = (const char*)(srcs[t4] + (size_t)rows[t4] * KDIM + k0);
        uint32_t sb = so + t4 * TILE_BYTES;
#pragma unroll
        for (int j = 0; j < 2; j++) {
            int chunk = tid * 2 + j;          // 0..511
            int r = chunk >> 2;               // row 0..127
            int cc = chunk & 3;               // 16B chunk in row
            cp_async16(sb + r * ROW_BYTES + cc * 16,
                       gb + (size_t)r * (KDIM * 2) + cc * 16);
        }
    }
}

__global__ __launch_bounds__(256, 1) void gemm_kernel(float* __restrict__ out) {
    extern __shared__ char smem[];
    const uint32_t sb = smem_u32(smem);
    const int tid = threadIdx.x;
    const int wid = tid >> 5;
    const int lane = tid & 31;
    const int warp_m = wid & 1;               // 2 x 64 rows
    const int warp_n = wid >> 1;              // 4 x 32 cols
    const int m0 = blockIdx.y * BM;
    const int n0 = blockIdx.x * BN;

    float acc[4][4][4];
#pragma unroll
    for (int a = 0; a < 4; a++)
#pragma unroll
        for (int b = 0; b < 4; b++)
#pragma unroll
            for (int c = 0; c < 4; c++) acc[a][b][c] = 0.f;

    // prologue: stages 0..2
    for (int s = 0; s < STAGES - 1; s++) {
        load_stage(sb, s, m0, n0, s * BK, tid);
        CP_COMMIT();
    }

    // per-lane ldmatrix row/col components
    const int lrow = lane & 15;               // row within 16
    const int lhalf = lane >> 4;              // 16B half (k chunk)

    for (int t = 0; t < KTILES; t++) {
        CP_WAIT2();
        __syncthreads();

        // prefetch stage t+3 into slot (t+3)%4 (was consumed at iter t-1)
        if (t + STAGES - 1 < KTILES)
            load_stage(sb, (t + STAGES - 1) & 3, m0, n0, (t + STAGES - 1) * BK, tid);
        CP_COMMIT();

        const uint32_t st = sb + (t & 3) * STAGE_BYTES;
        const uint32_t Ah = st;
        const uint32_t Al = st + TILE_BYTES;
        const uint32_t Bh = st + 2 * TILE_BYTES;
        const uint32_t Bl = st + 3 * TILE_BYTES;

#pragma unroll
        for (int ks = 0; ks < 2; ks++) {
            const int cc = ks * 2 + lhalf;     // 16B chunk index in row
            uint32_t ah[4][4], al[4][4];
#pragma unroll
            for (int mt = 0; mt < 4; mt++) {
                const int r = warp_m * 64 + mt * 16 + lrow;
                ldsm4(ah[mt], Ah + r * ROW_BYTES + cc * 16);
                ldsm4(al[mt], Al + r * ROW_BYTES + cc * 16);
            }
            uint32_t bh0[4], bh1[4], bl0[4], bl1[4];
#pragma unroll
            for (int np = 0; np < 2; np++) {
                const int r = warp_n * 32 + np * 16 + lrow;
                uint32_t q[4];
                ldsm4(q, Bh + r * ROW_BYTES + cc * 16);
                bh0[2 * np] = q[0]; bh0[2 * np + 1] = q[1];
                bh1[2 * np] = q[2]; bh1[2 * np + 1] = q[3];
                ldsm4(q, Bl + r * ROW_BYTES + cc * 16);
                bl0[2 * np] = q[0]; bl0[2 * np + 1] = q[1];
                bl1[2 * np] = q[2]; bl1[2 * np + 1] = q[3];
            }
#pragma unroll
            for (int mt = 0; mt < 4; mt++) {
#pragma unroll
                for (int nt = 0; nt < 4; nt++) {
                    mma16816(acc[mt][nt], ah[mt], bh0[nt], bh1[nt]);  // hi*hi
                    mma16816(acc[mt][nt], ah[mt], bl0[nt], bl1[nt]);  // hi*lo
                    mma16816(acc[mt][nt], al[mt], bh0[nt], bh1[nt]);  // lo*hi
                }
            }
        }
        __syncthreads();
    }

    // ---- epilogue: per-row 32-col multivector rsqrt normalization ----
    const int gid = lane >> 2;     // 0..7 row-in-8
    const int qid = lane & 3;      // quad lane -> col pair
#pragma unroll
    for (int mt = 0; mt < 4; mt++) {
        float su = 0.f, sd = 0.f;
#pragma unroll
        for (int nt = 0; nt < 4; nt++) {
            su += acc[mt][nt][0] * acc[mt][nt][0] + acc[mt][nt][1] * acc[mt][nt][1];
            sd += acc[mt][nt][2] * acc[mt][nt][2] + acc[mt][nt][3] * acc[mt][nt][3];
        }
        su += __shfl_xor_sync(0xffffffffu, su, 1);
        su += __shfl_xor_sync(0xffffffffu, su, 2);
        sd += __shfl_xor_sync(0xffffffffu, sd, 1);
        sd += __shfl_xor_sync(0xffffffffu, sd, 2);
        const float invu = rsqrtf(su + 1e-6f);
        const float invd = rsqrtf(sd + 1e-6f);
        const int ru = m0 + warp_m * 64 + mt * 16 + gid;
        const int rd = ru + 8;
#pragma unroll
        for (int nt = 0; nt < 4; nt++) {
            const int col = n0 + warp_n * 32 + nt * 8 + qid * 2;
            float2 u2 = make_float2(acc[mt][nt][0] * invu, acc[mt][nt][1] * invu);
            float2 d2 = make_float2(acc[mt][nt][2] * invd, acc[mt][nt][3] * invd);
            *(float2*)(out + (size_t)ru * NDIM + col) = u2;
            *(float2*)(out + (size_t)rd * NDIM + col) = d2;
        }
    }
}

// ---------------- launch ----------------
extern "C" void kernel_launch(void* const* d_in, const int* in_sizes, int n_in,
                              void* d_out, int out_size) {
    (void)in_sizes; (void)n_in; (void)out_size;
    const float* x = (const float*)d_in[0];
    const float* w = (const float*)d_in[1];
    float* out = (float*)d_out;

    k_split_x<<<(MDIM * (KDIM / 4)) / 256, 256>>>((const float4*)x);
    k_build_w<<<(unsigned)(((size_t)NDIM * KDIM) / 256), 256>>>(w);

    static bool attr_set = false;
    if (!attr_set) {
        cudaFuncSetAttribute(gemm_kernel, cudaFuncAttributeMaxDynamicSharedMemorySize,
                             SMEM_BYTES);
        attr_set = true;
    }
    gemm_kernel<<<dim3(NDIM / BN, MDIM / BM), 256, SMEM_BYTES>>>(out);
}

// round 5
// speedup vs baseline: 2.6599x; 2.6599x over previous
#include <cuda_runtime.h>
#include <cuda_fp16.h>
#include <cstdint>

// Problem dims
#define MDIM 4096       // batch
#define KDIM 4096       // IN_F * 32
#define NDIM 4096       // OUT_F * 32
#define BM 128
#define BN 128
#define BK 32
#define KTILES (KDIM / BK)   // 128
#define STAGES 4

// SMEM tile geometry: rows of 32 fp16 = 64B data, padded to 80B stride
// (20*r mod 32 is a permutation for r in 0..7 -> conflict-free ldmatrix)
#define ROW_BYTES 80
#define TILE_BYTES (128 * ROW_BYTES)          // 10240
#define STAGE_BYTES (2 * TILE_BYTES)          // Ah|Bh = 20480
#define SMEM_BYTES (STAGES * STAGE_BYTES)     // 81920

// 64 MB static scratch (sanctioned __device__ globals)
__device__ __align__(128) __half g_Ah[(size_t)MDIM * KDIM];
__device__ __align__(128) __half g_Bh[(size_t)NDIM * KDIM];

// ---------------- helpers ----------------
__device__ __forceinline__ uint32_t smem_u32(const void* p) {
    uint32_t a;
    asm("{ .reg .u64 t; cvta.to.shared.u64 t, %1; cvt.u32.u64 %0, t; }" : "=r"(a) : "l"(p));
    return a;
}
__device__ __forceinline__ void cp_async16(uint32_t s, const void* g) {
    asm volatile("cp.async.cg.shared.global [%0], [%1], 16;" :: "r"(s), "l"(g));
}
#define CP_COMMIT() asm volatile("cp.async.commit_group;" ::: "memory")
#define CP_WAIT2()  asm volatile("cp.async.wait_group 2;" ::: "memory")

__device__ __forceinline__ void ldsm4(uint32_t (&r)[4], uint32_t addr) {
    asm volatile("ldmatrix.sync.aligned.m8n8.x4.shared.b16 {%0,%1,%2,%3}, [%4];"
                 : "=r"(r[0]), "=r"(r[1]), "=r"(r[2]), "=r"(r[3]) : "r"(addr));
}
__device__ __forceinline__ void mma16816(float (&c)[4], const uint32_t (&a)[4],
                                         uint32_t b0, uint32_t b1) {
    asm volatile("mma.sync.aligned.m16n8k16.row.col.f32.f16.f16.f32 "
                 "{%0,%1,%2,%3}, {%4,%5,%6,%7}, {%8,%9}, {%0,%1,%2,%3};"
                 : "+f"(c[0]), "+f"(c[1]), "+f"(c[2]), "+f"(c[3])
                 : "r"(a[0]), "r"(a[1]), "r"(a[2]), "r"(a[3]), "r"(b0), "r"(b1));
}

// ---------------- pre-kernels ----------------
__global__ void k_split_x(const float4* __restrict__ x) {
    unsigned i = blockIdx.x * blockDim.x + threadIdx.x;   // 0 .. 4M-1
    float4 v = x[i];
    __half2 h01 = make_half2(__float2half_rn(v.x), __float2half_rn(v.y));
    __half2 h23 = make_half2(__float2half_rn(v.z), __float2half_rn(v.w));
    uint2 packed;
    packed.x = *reinterpret_cast<uint32_t*>(&h01);
    packed.y = *reinterpret_cast<uint32_t*>(&h23);
    reinterpret_cast<uint2*>(g_Ah)[i] = packed;
}

// Bbig[n = o*32+k, kdim = f*32+i] = sign(i, i^k) * W[o, f, i^k]
__global__ void k_build_w(const float* __restrict__ w) {
    unsigned idx = blockIdx.x * blockDim.x + threadIdx.x; // 0 .. 16M-1
    unsigned col = idx & 4095u;        // kdim
    unsigned row = idx >> 12;          // n
    unsigned i = col & 31u, f = col >> 5;
    unsigned k = row & 31u, o = row >> 5;
    unsigned j = i ^ k;
    float v = w[(o * 128u + f) * 32u + j];
    // reorder sign: sum popc((i>>t) & j), t=1..4 ; metric: bit 4 of (i & j) (sig[4] = -1)
    unsigned s = __popc((i >> 1) & j) + __popc((i >> 2) & j) +
                 __popc((i >> 3) & j) + __popc((i >> 4) & j);
    s += (i & j) >> 4;
    if (s & 1u) v = -v;
    g_Bh[idx] = __float2half_rn(v);
}

// ---------------- GEMM (mma.sync fp16, single term) ----------------
__device__ __forceinline__ void load_stage(uint32_t sbase, int slot, int m0, int n0,
                                           int k0, int tid) {
    const uint32_t so = sbase + slot * STAGE_BYTES;
    const __half* srcs[2] = {g_Ah, g_Bh};
    const int rows[2] = {m0, n0};
#pragma unroll
    for (int t2 = 0; t2 < 2; t2++) {
        const char* gb = (const char*)(srcs[t2] + (size_t)rows[t2] * KDIM + k0);
        uint32_t sdst = so + t2 * TILE_BYTES;
#pragma unroll
        for (int j = 0; j < 2; j++) {
            int chunk = tid * 2 + j;          // 0..511
            int r = chunk >> 2;               // row 0..127
            int cc = chunk & 3;               // 16B chunk in row
            cp_async16(sdst + r * ROW_BYTES + cc * 16,
                       gb + (size_t)r * (KDIM * 2) + cc * 16);
        }
    }
}

__global__ __launch_bounds__(256, 2) void gemm_kernel(float* __restrict__ out) {
    extern __shared__ char smem[];
    const uint32_t sb = smem_u32(smem);
    const int tid = threadIdx.x;
    const int wid = tid >> 5;
    const int lane = tid & 31;
    const int warp_m = wid & 1;               // 2 x 64 rows
    const int warp_n = wid >> 1;              // 4 x 32 cols
    const int m0 = blockIdx.y * BM;
    const int n0 = blockIdx.x * BN;

    float acc[4][4][4];
#pragma unroll
    for (int a = 0; a < 4; a++)
#pragma unroll
        for (int b = 0; b < 4; b++)
#pragma unroll
            for (int c = 0; c < 4; c++) acc[a][b][c] = 0.f;

    // prologue: stages 0..2
    for (int s = 0; s < STAGES - 1; s++) {
        load_stage(sb, s, m0, n0, s * BK, tid);
        CP_COMMIT();
    }

    // per-lane ldmatrix row/col components
    const int lrow = lane & 15;               // row within 16
    const int lhalf = lane >> 4;              // 16B half (k chunk)

    for (int t = 0; t < KTILES; t++) {
        CP_WAIT2();
        __syncthreads();

        // prefetch stage t+3 into slot (t+3)%4 (consumed at iter t-1)
        if (t + STAGES - 1 < KTILES)
            load_stage(sb, (t + STAGES - 1) & 3, m0, n0, (t + STAGES - 1) * BK, tid);
        CP_COMMIT();

        const uint32_t st = sb + (t & 3) * STAGE_BYTES;
        const uint32_t Ah = st;
        const uint32_t Bh = st + TILE_BYTES;

#pragma unroll
        for (int ks = 0; ks < 2; ks++) {
            const int cc = ks * 2 + lhalf;     // 16B chunk index in row
            uint32_t a[4][4];
#pragma unroll
            for (int mt = 0; mt < 4; mt++) {
                const int r = warp_m * 64 + mt * 16 + lrow;
                ldsm4(a[mt], Ah + r * ROW_BYTES + cc * 16);
            }
            uint32_t b0[4], b1[4];
#pragma unroll
            for (int np = 0; np < 2; np++) {
                const int r = warp_n * 32 + np * 16 + lrow;
                uint32_t q[4];
                ldsm4(q, Bh + r * ROW_BYTES + cc * 16);
                b0[2 * np] = q[0]; b0[2 * np + 1] = q[1];
                b1[2 * np] = q[2]; b1[2 * np + 1] = q[3];
            }
#pragma unroll
            for (int mt = 0; mt < 4; mt++) {
#pragma unroll
                for (int nt = 0; nt < 4; nt++) {
                    mma16816(acc[mt][nt], a[mt], b0[nt], b1[nt]);
                }
            }
        }
        __syncthreads();
    }

    // ---- epilogue: per-row 32-col multivector rsqrt normalization ----
    const int gid = lane >> 2;     // 0..7 row-in-8
    const int qid = lane & 3;      // quad lane -> col pair
#pragma unroll
    for (int mt = 0; mt < 4; mt++) {
        float su = 0.f, sd = 0.f;
#pragma unroll
        for (int nt = 0; nt < 4; nt++) {
            su += acc[mt][nt][0] * acc[mt][nt][0] + acc[mt][nt][1] * acc[mt][nt][1];
            sd += acc[mt][nt][2] * acc[mt][nt][2] + acc[mt][nt][3] * acc[mt][nt][3];
        }
        su += __shfl_xor_sync(0xffffffffu, su, 1);
        su += __shfl_xor_sync(0xffffffffu, su, 2);
        sd += __shfl_xor_sync(0xffffffffu, sd, 1);
        sd += __shfl_xor_sync(0xffffffffu, sd, 2);
        const float invu = rsqrtf(su + 1e-6f);
        const float invd = rsqrtf(sd + 1e-6f);
        const int ru = m0 + warp_m * 64 + mt * 16 + gid;
        const int rd = ru + 8;
#pragma unroll
        for (int nt = 0; nt < 4; nt++) {
            const int col = n0 + warp_n * 32 + nt * 8 + qid * 2;
            float2 u2 = make_float2(acc[mt][nt][0] * invu, acc[mt][nt][1] * invu);
            float2 d2 = make_float2(acc[mt][nt][2] * invd, acc[mt][nt][3] * invd);
            *(float2*)(out + (size_t)ru * NDIM + col) = u2;
            *(float2*)(out + (size_t)rd * NDIM + col) = d2;
        }
    }
}

// ---------------- launch ----------------
extern "C" void kernel_launch(void* const* d_in, const int* in_sizes, int n_in,
                              void* d_out, int out_size) {
    (void)in_sizes; (void)n_in; (void)out_size;
    const float* x = (const float*)d_in[0];
    const float* w = (const float*)d_in[1];
    float* out = (float*)d_out;

    k_split_x<<<(MDIM * (KDIM / 4)) / 256, 256>>>((const float4*)x);
    k_build_w<<<(unsigned)(((size_t)NDIM * KDIM) / 256), 256>>>(w);

    static bool attr_set = false;
    if (!attr_set) {
        cudaFuncSetAttribute(gemm_kernel, cudaFuncAttributeMaxDynamicSharedMemorySize,
                             SMEM_BYTES);
        attr_set = true;
    }
    gemm_kernel<<<dim3(NDIM / BN, MDIM / BM), 256, SMEM_BYTES>>>(out);
}

// round 6
// speedup vs baseline: 5.8692x; 2.2065x over previous
#include <cuda_runtime.h>
#include <cuda_fp16.h>
#include <cstdint>

// Problem dims
#define MDIM 4096            // batch
#define GM   16384           // GEMM M = batch*4 (matrix rows)
#define GK   1024            // GEMM K = 2(re/im) * 128(f) * 4(t)
#define GN   1024            // GEMM N = 128(o) * 4(c) * 2(re/im)
#define BM 128
#define BN 128
#define BK 32
#define KTILES (GK / BK)     // 32
#define STAGES 4

// SMEM tile geometry: rows of 32 fp16 = 64B data, padded to 80B stride
#define ROW_BYTES 80
#define TILE_BYTES (128 * ROW_BYTES)          // 10240
#define STAGE_BYTES (2 * TILE_BYTES)          // A|B = 20480
#define SMEM_BYTES (STAGES * STAGE_BYTES)     // 81920

// static scratch (sanctioned __device__ globals): 32 + 2 + 64 MB
__device__ __align__(128) __half g_A2[(size_t)GM * GK];
__device__ __align__(128) __half g_B2[(size_t)GN * GK];
__device__ __align__(128) float  g_C[(size_t)GM * GN];

// ---------- compile-time gamma tables (Cl(4,1) -> M4(C)) ----------
// gamma1=s1(x)s1, gamma2=s1(x)s2, gamma3=s1(x)s3, gamma4=s2(x)I, gamma5=-i s3(x)I
// Each blade Gamma_a is a phase-permutation matrix: column c -> row P_a(c),
// value i^{ph_a(c)}.
struct Tables {
    int   fw_a[16][8];     // entry (r*4+c): the 8 blades hitting it
    int   fw_ph[16][8];    // their phases (0:+1 1:+i 2:-1 3:-i)
    int   inv_row[32][4];  // per blade a, column c: row
    int   inv_c8[32][4];   // column in the 4x8 (re,im interleaved) block
    float inv_sgn[32][4];  // sign * 1/4
    constexpr Tables() : fw_a(), fw_ph(), inv_row(), inv_c8(), inv_sgn() {
        int cnt[16] = {};
        for (int a = 0; a < 32; a++) {
            for (int c = 0; c < 4; c++) {
                int r = c, ph = 0;
                for (int bit = 4; bit >= 0; bit--) {   // rightmost factor acts first
                    if (!((a >> bit) & 1)) continue;
                    int nr = r, pa = 0;
                    if      (bit == 0) { nr = r ^ 3; pa = 0; }
                    else if (bit == 1) { nr = r ^ 3; pa = (r & 1) ? 3 : 1; }
                    else if (bit == 2) { nr = r ^ 2; pa = (r & 1) ? 2 : 0; }
                    else if (bit == 3) { nr = r ^ 2; pa = (r & 2) ? 3 : 1; }
                    else               { nr = r;     pa = (r & 2) ? 1 : 3; }
                    r = nr; ph = (ph + pa) & 3;
                }
                int idx = r * 4 + c;
                fw_a[idx][cnt[idx]] = a;
                fw_ph[idx][cnt[idx]] = ph;
                cnt[idx]++;
                inv_row[a][c] = r;
                inv_c8[a][c]  = c * 2 + (ph & 1);
                inv_sgn[a][c] = (ph >= 2) ? -0.25f : 0.25f;
            }
        }
    }
};
__constant__ Tables TB = Tables();

// ---------------- helpers ----------------
__device__ __forceinline__ uint32_t smem_u32(const void* p) {
    uint32_t a;
    asm("{ .reg .u64 t; cvta.to.shared.u64 t, %1; cvt.u32.u64 %0, t; }" : "=r"(a) : "l"(p));
    return a;
}
__device__ __forceinline__ void cp_async16(uint32_t s, const void* g) {
    asm volatile("cp.async.cg.shared.global [%0], [%1], 16;" :: "r"(s), "l"(g));
}
#define CP_COMMIT() asm volatile("cp.async.commit_group;" ::: "memory")
#define CP_WAIT2()  asm volatile("cp.async.wait_group 2;" ::: "memory")

__device__ __forceinline__ void ldsm4(uint32_t (&r)[4], uint32_t addr) {
    asm volatile("ldmatrix.sync.aligned.m8n8.x4.shared.b16 {%0,%1,%2,%3}, [%4];"
                 : "=r"(r[0]), "=r"(r[1]), "=r"(r[2]), "=r"(r[3]) : "r"(addr));
}
__device__ __forceinline__ void mma16816(float (&c)[4], const uint32_t (&a)[4],
                                         uint32_t b0, uint32_t b1) {
    asm volatile("mma.sync.aligned.m16n8k16.row.col.f32.f16.f16.f32 "
                 "{%0,%1,%2,%3}, {%4,%5,%6,%7}, {%8,%9}, {%0,%1,%2,%3};"
                 : "+f"(c[0]), "+f"(c[1]), "+f"(c[2]), "+f"(c[3])
                 : "r"(a[0]), "r"(a[1]), "r"(a[2]), "r"(a[3]), "r"(b0), "r"(b1));
}
__device__ __forceinline__ uint32_t pack2h(float a, float b) {
    __half2 h = make_half2(__float2half_rn(a), __float2half_rn(b));
    return *reinterpret_cast<uint32_t*>(&h);
}

// ---------------- pre-kernels ----------------
// x[b,f,0..31] -> X matrix entries; A2[4b+r, u*512 + f*4 + t]
__global__ void k_build_A(const float* __restrict__ x) {
    unsigned tau = blockIdx.x * blockDim.x + threadIdx.x;   // 0 .. 524287
    unsigned b = tau >> 7, f = tau & 127u;
    float xv[32];
    const float4* xp = (const float4*)(x + ((size_t)b * 128 + f) * 32);
#pragma unroll
    for (int q = 0; q < 8; q++) {
        float4 v = xp[q];
        xv[q * 4 + 0] = v.x; xv[q * 4 + 1] = v.y; xv[q * 4 + 2] = v.z; xv[q * 4 + 3] = v.w;
    }
#pragma unroll
    for (int r = 0; r < 4; r++) {
        float re[4], im[4];
#pragma unroll
        for (int t = 0; t < 4; t++) {
            float rr = 0.f, ii = 0.f;
#pragma unroll
            for (int e = 0; e < 8; e++) {
                int a  = TB.fw_a[r * 4 + t][e];
                int ph = TB.fw_ph[r * 4 + t][e];
                float v = xv[a];
                if (ph == 0) rr += v; else if (ph == 1) ii += v;
                else if (ph == 2) rr -= v; else ii -= v;
            }
            re[t] = rr; im[t] = ii;
        }
        size_t row = (size_t)(b * 4 + r) * GK;
        uint2 pre = make_uint2(pack2h(re[0], re[1]), pack2h(re[2], re[3]));
        uint2 pim = make_uint2(pack2h(im[0], im[1]), pack2h(im[2], im[3]));
        *(uint2*)(g_A2 + row + f * 4)       = pre;
        *(uint2*)(g_A2 + row + 512 + f * 4) = pim;
    }
}

// W[o,f,0..31] -> Wm; B2[n = o*8 + c*2 + v, u*512 + f*4 + t]
//   v=0 (Re out): u0 = Re Wm[t,c], u1 = -Im Wm[t,c]
//   v=1 (Im out): u0 = Im Wm[t,c], u1 =  Re Wm[t,c]
__global__ void k_build_w2(const float* __restrict__ w) {
    unsigned tau = blockIdx.x * blockDim.x + threadIdx.x;   // 0 .. 16383
    unsigned o = tau >> 7, f = tau & 127u;
    float wv[32];
    const float4* wp = (const float4*)(w + ((size_t)o * 128 + f) * 32);
#pragma unroll
    for (int q = 0; q < 8; q++) {
        float4 v = wp[q];
        wv[q * 4 + 0] = v.x; wv[q * 4 + 1] = v.y; wv[q * 4 + 2] = v.z; wv[q * 4 + 3] = v.w;
    }
    float re[4][4], im[4][4];   // [t][c]
#pragma unroll
    for (int t = 0; t < 4; t++)
#pragma unroll
        for (int c = 0; c < 4; c++) {
            float rr = 0.f, ii = 0.f;
#pragma unroll
            for (int e = 0; e < 8; e++) {
                int a  = TB.fw_a[t * 4 + c][e];
                int ph = TB.fw_ph[t * 4 + c][e];
                float v = wv[a];
                if (ph == 0) rr += v; else if (ph == 1) ii += v;
                else if (ph == 2) rr -= v; else ii -= v;
            }
            re[t][c] = rr; im[t][c] = ii;
        }
#pragma unroll
    for (int c = 0; c < 4; c++)
#pragma unroll
        for (int v = 0; v < 2; v++) {
            size_t row = (size_t)(o * 8 + c * 2 + v) * GK;
            float u0[4], u1[4];
#pragma unroll
            for (int t = 0; t < 4; t++) {
                u0[t] = v ? im[t][c] :  re[t][c];
                u1[t] = v ? re[t][c] : -im[t][c];
            }
            *(uint2*)(g_B2 + row + f * 4)       = make_uint2(pack2h(u0[0], u0[1]), pack2h(u0[2], u0[3]));
            *(uint2*)(g_B2 + row + 512 + f * 4) = make_uint2(pack2h(u1[0], u1[1]), pack2h(u1[2], u1[3]));
        }
}

// ---------------- GEMM (mma.sync fp16) ----------------
__device__ __forceinline__ void load_stage(uint32_t sbase, int slot, int m0, int n0,
                                           int k0, int tid) {
    const uint32_t so = sbase + slot * STAGE_BYTES;
    const __half* srcs[2] = {g_A2, g_B2};
    const int rows[2] = {m0, n0};
#pragma unroll
    for (int t2 = 0; t2 < 2; t2++) {
        const char* gb = (const char*)(srcs[t2] + (size_t)rows[t2] * GK + k0);
        uint32_t sdst = so + t2 * TILE_BYTES;
#pragma unroll
        for (int j = 0; j < 2; j++) {
            int chunk = tid * 2 + j;          // 0..511
            int r = chunk >> 2;               // row 0..127
            int cc = chunk & 3;               // 16B chunk in row
            cp_async16(sdst + r * ROW_BYTES + cc * 16,
                       gb + (size_t)r * (GK * 2) + cc * 16);
        }
    }
}

__global__ __launch_bounds__(256, 2) void gemm_kernel() {
    extern __shared__ char smem[];
    const uint32_t sb = smem_u32(smem);
    const int tid = threadIdx.x;
    const int wid = tid >> 5;
    const int lane = tid & 31;
    const int warp_m = wid & 1;               // 2 x 64 rows
    const int warp_n = wid >> 1;              // 4 x 32 cols
    const int m0 = blockIdx.y * BM;
    const int n0 = blockIdx.x * BN;

    float acc[4][4][4];
#pragma unroll
    for (int a = 0; a < 4; a++)
#pragma unroll
        for (int b = 0; b < 4; b++)
#pragma unroll
            for (int c = 0; c < 4; c++) acc[a][b][c] = 0.f;

    for (int s = 0; s < STAGES - 1; s++) {
        load_stage(sb, s, m0, n0, s * BK, tid);
        CP_COMMIT();
    }

    const int lrow = lane & 15;
    const int lhalf = lane >> 4;

    for (int t = 0; t < KTILES; t++) {
        CP_WAIT2();
        __syncthreads();

        if (t + STAGES - 1 < KTILES)
            load_stage(sb, (t + STAGES - 1) & 3, m0, n0, (t + STAGES - 1) * BK, tid);
        CP_COMMIT();

        const uint32_t st = sb + (t & 3) * STAGE_BYTES;
        const uint32_t Ah = st;
        const uint32_t Bh = st + TILE_BYTES;

#pragma unroll
        for (int ks = 0; ks < 2; ks++) {
            const int cc = ks * 2 + lhalf;
            uint32_t a[4][4];
#pragma unroll
            for (int mt = 0; mt < 4; mt++) {
                const int r = warp_m * 64 + mt * 16 + lrow;
                ldsm4(a[mt], Ah + r * ROW_BYTES + cc * 16);
            }
            uint32_t b0[4], b1[4];
#pragma unroll
            for (int np = 0; np < 2; np++) {
                const int r = warp_n * 32 + np * 16 + lrow;
                uint32_t q[4];
                ldsm4(q, Bh + r * ROW_BYTES + cc * 16);
                b0[2 * np] = q[0]; b0[2 * np + 1] = q[1];
                b1[2 * np] = q[2]; b1[2 * np + 1] = q[3];
            }
#pragma unroll
            for (int mt = 0; mt < 4; mt++)
#pragma unroll
                for (int nt = 0; nt < 4; nt++)
                    mma16816(acc[mt][nt], a[mt], b0[nt], b1[nt]);
        }
        __syncthreads();
    }

    // write raw C tile (no normalization here)
    const int gid = lane >> 2;
    const int qid = lane & 3;
#pragma unroll
    for (int mt = 0; mt < 4; mt++) {
        const int ru = m0 + warp_m * 64 + mt * 16 + gid;
        const int rd = ru + 8;
#pragma unroll
        for (int nt = 0; nt < 4; nt++) {
            const int col = n0 + warp_n * 32 + nt * 8 + qid * 2;
            *(float2*)(g_C + (size_t)ru * GN + col) = make_float2(acc[mt][nt][0], acc[mt][nt][1]);
            *(float2*)(g_C + (size_t)rd * GN + col) = make_float2(acc[mt][nt][2], acc[mt][nt][3]);
        }
    }
}

// ---------------- epilogue: inverse rep transform + normalize ----------------
__global__ void k_finish(float* __restrict__ out) {
    unsigned tau = blockIdx.x * blockDim.x + threadIdx.x;   // 0 .. 524287
    unsigned b = tau >> 7, o = tau & 127u;
    float blk[4][8];
#pragma unroll
    for (int r = 0; r < 4; r++) {
        const float4* p = (const float4*)(g_C + (size_t)(b * 4 + r) * GN + o * 8);
        float4 v0 = p[0], v1 = p[1];
        blk[r][0] = v0.x; blk[r][1] = v0.y; blk[r][2] = v0.z; blk[r][3] = v0.w;
        blk[r][4] = v1.x; blk[r][5] = v1.y; blk[r][6] = v1.z; blk[r][7] = v1.w;
    }
    float y[32];
    float ssum = 0.f;
#pragma unroll
    for (int a = 0; a < 32; a++) {
        float s = 0.f;
#pragma unroll
        for (int c = 0; c < 4; c++)
            s += TB.inv_sgn[a][c] * blk[TB.inv_row[a][c]][TB.inv_c8[a][c]];
        y[a] = s;
        ssum += s * s;
    }
    const float inv = rsqrtf(ssum + 1e-6f);
    float* op = out + (size_t)b * 4096 + o * 32;
#pragma unroll
    for (int a = 0; a < 32; a += 4)
        *(float4*)(op + a) = make_float4(y[a] * inv, y[a + 1] * inv, y[a + 2] * inv, y[a + 3] * inv);
}

// ---------------- launch ----------------
extern "C" void kernel_launch(void* const* d_in, const int* in_sizes, int n_in,
                              void* d_out, int out_size) {
    (void)in_sizes; (void)n_in; (void)out_size;
    const float* x = (const float*)d_in[0];
    const float* w = (const float*)d_in[1];
    float* out = (float*)d_out;

    k_build_A<<<524288 / 256, 256>>>(x);
    k_build_w2<<<16384 / 256, 256>>>(w);

    static bool attr_set = false;
    if (!attr_set) {
        cudaFuncSetAttribute(gemm_kernel, cudaFuncAttributeMaxDynamicSharedMemorySize,
                             SMEM_BYTES);
        attr_set = true;
    }
    gemm_kernel<<<dim3(GN / BN, GM / BM), 256, SMEM_BYTES>>>();
    k_finish<<<524288 / 256, 256>>>(out);
}

// round 9
// speedup vs baseline: 6.1020x; 1.0397x over previous
#include <cuda_runtime.h>
#include <cuda_fp16.h>
#include <cstdint>

// Problem dims
#define MDIM 4096            // batch
#define GM   16384           // GEMM M = batch*4 (matrix rows)
#define GK   1024            // GEMM K = 2(re/im) * 128(f) * 4(t)
#define GN   1024            // GEMM N = 128(o) * 4(c) * 2(re/im)
#define BM 128
#define BN 128
#define BK 32
#define KTILES (GK / BK)     // 32
#define STAGES 4

// SMEM tile geometry: rows of 32 fp16 = 64B data, padded to 80B stride
#define ROW_BYTES 80
#define TILE_BYTES (128 * ROW_BYTES)          // 10240
#define STAGE_BYTES (2 * TILE_BYTES)          // A|B = 20480
#define SMEM_BYTES (STAGES * STAGE_BYTES)     // 81920  (also >= 128*132*4 = 67584 for epilogue)
#define EPI_STRIDE 132                        // floats per staged row

// static scratch (sanctioned __device__ globals): 32 + 2 MB
__device__ __align__(128) __half g_A2[(size_t)GM * GK];
__device__ __align__(128) __half g_B2[(size_t)GN * GK];

// ---------- compile-time gamma tables (Cl(4,1) -> M4(C)) ----------
// gamma1=s1(x)s1, gamma2=s1(x)s2, gamma3=s1(x)s3, gamma4=s2(x)I, gamma5=-i s3(x)I
// Each blade Gamma_a is a phase-permutation matrix: column c -> row P_a(c),
// value i^{ph_a(c)}.
struct Tables {
    int   fw_a[16][8];     // entry (r*4+c): the 8 blades hitting it
    int   fw_ph[16][8];    // their phases (0:+1 1:+i 2:-1 3:-i)
    int   inv_row[32][4];  // per blade a, column c: row
    int   inv_c8[32][4];   // column in the 4x8 (re,im interleaved) block
    float inv_sgn[32][4];  // sign * 1/4
    constexpr Tables() : fw_a(), fw_ph(), inv_row(), inv_c8(), inv_sgn() {
        int cnt[16] = {};
        for (int a = 0; a < 32; a++) {
            for (int c = 0; c < 4; c++) {
                int r = c, ph = 0;
                for (int bit = 4; bit >= 0; bit--) {   // rightmost factor acts first
                    if (!((a >> bit) & 1)) continue;
                    int nr = r, pa = 0;
                    if      (bit == 0) { nr = r ^ 3; pa = 0; }
                    else if (bit == 1) { nr = r ^ 3; pa = (r & 1) ? 3 : 1; }
                    else if (bit == 2) { nr = r ^ 2; pa = (r & 1) ? 2 : 0; }
                    else if (bit == 3) { nr = r ^ 2; pa = (r & 2) ? 3 : 1; }
                    else               { nr = r;     pa = (r & 2) ? 1 : 3; }
                    r = nr; ph = (ph + pa) & 3;
                }
                int idx = r * 4 + c;
                fw_a[idx][cnt[idx]] = a;
                fw_ph[idx][cnt[idx]] = ph;
                cnt[idx]++;
                inv_row[a][c] = r;
                inv_c8[a][c]  = c * 2 + (ph & 1);
                inv_sgn[a][c] = (ph >= 2) ? -0.25f : 0.25f;
            }
        }
    }
};
__constant__ Tables TB = Tables();

// ---------------- helpers ----------------
__device__ __forceinline__ uint32_t smem_u32(const void* p) {
    uint32_t a;
    asm("{ .reg .u64 t; cvta.to.shared.u64 t, %1; cvt.u32.u64 %0, t; }" : "=r"(a) : "l"(p));
    return a;
}
__device__ __forceinline__ void cp_async16(uint32_t s, const void* g) {
    asm volatile("cp.async.cg.shared.global [%0], [%1], 16;" :: "r"(s), "l"(g));
}
#define CP_COMMIT() asm volatile("cp.async.commit_group;" ::: "memory")
#define CP_WAIT2()  asm volatile("cp.async.wait_group 2;" ::: "memory")

__device__ __forceinline__ void ldsm4(uint32_t (&r)[4], uint32_t addr) {
    asm volatile("ldmatrix.sync.aligned.m8n8.x4.shared.b16 {%0,%1,%2,%3}, [%4];"
                 : "=r"(r[0]), "=r"(r[1]), "=r"(r[2]), "=r"(r[3]) : "r"(addr));
}
__device__ __forceinline__ void mma16816(float (&c)[4], const uint32_t (&a)[4],
                                         uint32_t b0, uint32_t b1) {
    asm volatile("mma.sync.aligned.m16n8k16.row.col.f32.f16.f16.f32 "
                 "{%0,%1,%2,%3}, {%4,%5,%6,%7}, {%8,%9}, {%0,%1,%2,%3};"
                 : "+f"(c[0]), "+f"(c[1]), "+f"(c[2]), "+f"(c[3])
                 : "r"(a[0]), "r"(a[1]), "r"(a[2]), "r"(a[3]), "r"(b0), "r"(b1));
}
__device__ __forceinline__ uint32_t pack2h(float a, float b) {
    __half2 h = make_half2(__float2half_rn(a), __float2half_rn(b));
    return *reinterpret_cast<uint32_t*>(&h);
}

// ---------------- pre-kernels ----------------
// x[b,f,0..31] -> X matrix entries; A2[4b+r, u*512 + f*4 + t]
__global__ void k_build_A(const float* __restrict__ x) {
    unsigned tau = blockIdx.x * blockDim.x + threadIdx.x;   // 0 .. 524287
    unsigned b = tau >> 7, f = tau & 127u;
    float xv[32];
    const float4* xp = (const float4*)(x + ((size_t)b * 128 + f) * 32);
#pragma unroll
    for (int q = 0; q < 8; q++) {
        float4 v = xp[q];
        xv[q * 4 + 0] = v.x; xv[q * 4 + 1] = v.y; xv[q * 4 + 2] = v.z; xv[q * 4 + 3] = v.w;
    }
#pragma unroll
    for (int r = 0; r < 4; r++) {
        float re[4], im[4];
#pragma unroll
        for (int t = 0; t < 4; t++) {
            float rr = 0.f, ii = 0.f;
#pragma unroll
            for (int e = 0; e < 8; e++) {
                int a  = TB.fw_a[r * 4 + t][e];
                int ph = TB.fw_ph[r * 4 + t][e];
                float v = xv[a];
                if (ph == 0) rr += v; else if (ph == 1) ii += v;
                else if (ph == 2) rr -= v; else ii -= v;
            }
            re[t] = rr; im[t] = ii;
        }
        size_t row = (size_t)(b * 4 + r) * GK;
        uint2 pre = make_uint2(pack2h(re[0], re[1]), pack2h(re[2], re[3]));
        uint2 pim = make_uint2(pack2h(im[0], im[1]), pack2h(im[2], im[3]));
        *(uint2*)(g_A2 + row + f * 4)       = pre;
        *(uint2*)(g_A2 + row + 512 + f * 4) = pim;
    }
}

// W[o,f,0..31] -> Wm; B2[n = o*8 + c*2 + v, u*512 + f*4 + t]
//   v=0 (Re out): u0 = Re Wm[t,c], u1 = -Im Wm[t,c]
//   v=1 (Im out): u0 = Im Wm[t,c], u1 =  Re Wm[t,c]
__global__ void k_build_w2(const float* __restrict__ w) {
    unsigned tau = blockIdx.x * blockDim.x + threadIdx.x;   // 0 .. 16383
    unsigned o = tau >> 7, f = tau & 127u;
    float wv[32];
    const float4* wp = (const float4*)(w + ((size_t)o * 128 + f) * 32);
#pragma unroll
    for (int q = 0; q < 8; q++) {
        float4 v = wp[q];
        wv[q * 4 + 0] = v.x; wv[q * 4 + 1] = v.y; wv[q * 4 + 2] = v.z; wv[q * 4 + 3] = v.w;
    }
    float re[4][4], im[4][4];   // [t][c]
#pragma unroll
    for (int t = 0; t < 4; t++)
#pragma unroll
        for (int c = 0; c < 4; c++) {
            float rr = 0.f, ii = 0.f;
#pragma unroll
            for (int e = 0; e < 8; e++) {
                int a  = TB.fw_a[t * 4 + c][e];
                int ph = TB.fw_ph[t * 4 + c][e];
                float v = wv[a];
                if (ph == 0) rr += v; else if (ph == 1) ii += v;
                else if (ph == 2) rr -= v; else ii -= v;
            }
            re[t][c] = rr; im[t][c] = ii;
        }
#pragma unroll
    for (int c = 0; c < 4; c++)
#pragma unroll
        for (int v = 0; v < 2; v++) {
            size_t row = (size_t)(o * 8 + c * 2 + v) * GK;
            float u0[4], u1[4];
#pragma unroll
            for (int t = 0; t < 4; t++) {
                u0[t] = v ? im[t][c] :  re[t][c];
                u1[t] = v ? re[t][c] : -im[t][c];
            }
            *(uint2*)(g_B2 + row + f * 4)       = make_uint2(pack2h(u0[0], u0[1]), pack2h(u0[2], u0[3]));
            *(uint2*)(g_B2 + row + 512 + f * 4) = make_uint2(pack2h(u1[0], u1[1]), pack2h(u1[2], u1[3]));
        }
}

// ---------------- GEMM (mma.sync fp16) with fused epilogue ----------------
__device__ __forceinline__ void load_stage(uint32_t sbase, int slot, int m0, int n0,
                                           int k0, int tid) {
    const uint32_t so = sbase + slot * STAGE_BYTES;
    const __half* srcs[2] = {g_A2, g_B2};
    const int rows[2] = {m0, n0};
#pragma unroll
    for (int t2 = 0; t2 < 2; t2++) {
        const char* gb = (const char*)(srcs[t2] + (size_t)rows[t2] * GK + k0);
        uint32_t sdst = so + t2 * TILE_BYTES;
#pragma unroll
        for (int j = 0; j < 2; j++) {
            int chunk = tid * 2 + j;          // 0..511
            int r = chunk >> 2;               // row 0..127
            int cc = chunk & 3;               // 16B chunk in row
            cp_async16(sdst + r * ROW_BYTES + cc * 16,
                       gb + (size_t)r * (GK * 2) + cc * 16);
        }
    }
}

__global__ __launch_bounds__(256, 2) void gemm_kernel(float* __restrict__ out) {
    extern __shared__ char smem[];
    const uint32_t sb = smem_u32(smem);
    const int tid = threadIdx.x;
    const int wid = tid >> 5;
    const int lane = tid & 31;
    const int warp_m = wid & 1;               // 2 x 64 rows
    const int warp_n = wid >> 1;              // 4 x 32 cols
    const int m0 = blockIdx.y * BM;
    const int n0 = blockIdx.x * BN;

    float acc[4][4][4];
#pragma unroll
    for (int a = 0; a < 4; a++)
#pragma unroll
        for (int b = 0; b < 4; b++)
#pragma unroll
            for (int c = 0; c < 4; c++) acc[a][b][c] = 0.f;

    for (int s = 0; s < STAGES - 1; s++) {
        load_stage(sb, s, m0, n0, s * BK, tid);
        CP_COMMIT();
    }

    const int lrow = lane & 15;
    const int lhalf = lane >> 4;

    for (int t = 0; t < KTILES; t++) {
        CP_WAIT2();
        __syncthreads();

        if (t + STAGES - 1 < KTILES)
            load_stage(sb, (t + STAGES - 1) & 3, m0, n0, (t + STAGES - 1) * BK, tid);
        CP_COMMIT();

        const uint32_t st = sb + (t & 3) * STAGE_BYTES;
        const uint32_t Ah = st;
        const uint32_t Bh = st + TILE_BYTES;

#pragma unroll
        for (int ks = 0; ks < 2; ks++) {
            const int cc = ks * 2 + lhalf;
            uint32_t a[4][4];
#pragma unroll
            for (int mt = 0; mt < 4; mt++) {
                const int r = warp_m * 64 + mt * 16 + lrow;
                ldsm4(a[mt], Ah + r * ROW_BYTES + cc * 16);
            }
            uint32_t b0[4], b1[4];
#pragma unroll
            for (int np = 0; np < 2; np++) {
                const int r = warp_n * 32 + np * 16 + lrow;
                uint32_t q[4];
                ldsm4(q, Bh + r * ROW_BYTES + cc * 16);
                b0[2 * np] = q[0]; b0[2 * np + 1] = q[1];
                b1[2 * np] = q[2]; b1[2 * np + 1] = q[3];
            }
#pragma unroll
            for (int mt = 0; mt < 4; mt++)
#pragma unroll
                for (int nt = 0; nt < 4; nt++)
                    mma16816(acc[mt][nt], a[mt], b0[nt], b1[nt]);
        }
        __syncthreads();
    }

    // drain async pipe before repurposing SMEM
    asm volatile("cp.async.wait_group 0;" ::: "memory");
    __syncthreads();

    // ---- fused epilogue ----
    // stage the 128x128 fp32 C tile into SMEM (stride EPI_STRIDE floats)
    float* cs = (float*)smem;
    const int gid = lane >> 2;
    const int qid = lane & 3;
#pragma unroll
    for (int mt = 0; mt < 4; mt++) {
        const int r0 = warp_m * 64 + mt * 16 + gid;
        const int r1 = r0 + 8;
#pragma unroll
        for (int nt = 0; nt < 4; nt++) {
            const int col = warp_n * 32 + nt * 8 + qid * 2;
            cs[r0 * EPI_STRIDE + col]     = acc[mt][nt][0];
            cs[r0 * EPI_STRIDE + col + 1] = acc[mt][nt][1];
            cs[r1 * EPI_STRIDE + col]     = acc[mt][nt][2];
            cs[r1 * EPI_STRIDE + col + 1] = acc[mt][nt][3];
        }
    }
    __syncthreads();

    // each thread finishes 2 multivector blocks (32 batches x 16 o's per tile)
    const int b_base = m0 >> 2;    // global batch base of this tile
    const int o_base = n0 >> 3;    // global o base of this tile
#pragma unroll
    for (int it = 0; it < 2; it++) {
        const int blk = tid * 2 + it;          // 0..511
        const int b_local = blk >> 4;          // 0..31
        const int o_local = blk & 15;          // 0..15
        float blkv[4][8];
#pragma unroll
        for (int r = 0; r < 4; r++) {
            const float* rp = cs + (b_local * 4 + r) * EPI_STRIDE + o_local * 8;
#pragma unroll
            for (int c8 = 0; c8 < 8; c8++) blkv[r][c8] = rp[c8];
        }
        float y[32];
        float ssum = 0.f;
#pragma unroll
        for (int a = 0; a < 32; a++) {
            float s = 0.f;
#pragma unroll
            for (int c = 0; c < 4; c++)
                s += TB.inv_sgn[a][c] * blkv[TB.inv_row[a][c]][TB.inv_c8[a][c]];
            y[a] = s;
            ssum += s * s;
        }
        const float inv = rsqrtf(ssum + 1e-6f);
        float* op = out + (size_t)(b_base + b_local) * 4096 + (o_base + o_local) * 32;
#pragma unroll
        for (int a = 0; a < 32; a += 4)
            *(float4*)(op + a) = make_float4(y[a] * inv, y[a + 1] * inv,
                                             y[a + 2] * inv, y[a + 3] * inv);
    }
}

// ---------------- launch ----------------
extern "C" void kernel_launch(void* const* d_in, const int* in_sizes, int n_in,
                              void* d_out, int out_size) {
    (void)in_sizes; (void)n_in; (void)out_size;
    const float* x = (const float*)d_in[0];
    const float* w = (const float*)d_in[1];
    float* out = (float*)d_out;

    k_build_A<<<524288 / 256, 256>>>(x);
    k_build_w2<<<16384 / 256, 256>>>(w);

    static bool attr_set = false;
    if (!attr_set) {
        cudaFuncSetAttribute(gemm_kernel, cudaFuncAttributeMaxDynamicSharedMemorySize,
                             SMEM_BYTES);
        attr_set = true;
    }
    gemm_kernel<<<dim3(GN / BN, GM / BM), 256, SMEM_BYTES>>>(out);
}